// round 2
// baseline (speedup 1.0000x reference)
#include <cuda_runtime.h>
#include <math.h>

#define NN 200000
#define NE 800000
#define NG 8192
#define HD 128
#define NMT 64          // nodes per block tile in GEMM kernels

// ---------------- scratch (static device allocations; no cudaMalloc) ----------
__device__ float g_h[(size_t)NN * HD];     // node features          (~102 MB)
__device__ float g_z[(size_t)NN * HD];     // h + scattered messages (~102 MB)
__device__ float g_sums[NG * HD];          // pooled sums
__device__ float g_cnt[NG];                // pooled counts

__device__ __forceinline__ void red_add_v4(float* p, float4 v) {
    asm volatile("red.global.add.v4.f32 [%0], {%1,%2,%3,%4};"
                 :: "l"(p), "f"(v.x), "f"(v.y), "f"(v.z), "f"(v.w) : "memory");
}

// ---------------- encoder: h = x @ W_enc + b_enc  (K=78) ----------------------
__global__ void __launch_bounds__(128, 1)
encoder_kernel(const float* __restrict__ x,
               const float* __restrict__ W,
               const float* __restrict__ b) {
    extern __shared__ float sm[];
    float* Ws = sm;              // 78*128
    float* xt = Ws + 78 * HD;    // 78*NMT, k-major
    const int tid = threadIdx.x;
    const int node0 = blockIdx.x * NMT;

    const float4* Wg4 = (const float4*)W;
    float4* Ws4 = (float4*)Ws;
    for (int i = tid; i < 78 * (HD / 4); i += 128) Ws4[i] = Wg4[i];
    for (int idx = tid; idx < 78 * NMT; idx += 128) {
        int m = idx / 78, k = idx - m * 78;
        xt[k * NMT + m] = x[(size_t)(node0 + m) * 78 + k];
    }
    __syncthreads();

    const int r = tid >> 4, c = tid & 15;
    float acc[8][8];
#pragma unroll
    for (int j = 0; j < 8; j++) {
        float bb = b[c * 8 + j];
#pragma unroll
        for (int i = 0; i < 8; i++) acc[i][j] = bb;
    }
#pragma unroll 2
    for (int k = 0; k < 78; k++) {
        float4 a0 = *(float4*)&xt[k * NMT + r * 8];
        float4 a1 = *(float4*)&xt[k * NMT + r * 8 + 4];
        float4 w0 = *(float4*)&Ws[k * HD + c * 8];
        float4 w1 = *(float4*)&Ws[k * HD + c * 8 + 4];
        float a[8] = {a0.x, a0.y, a0.z, a0.w, a1.x, a1.y, a1.z, a1.w};
        float w[8] = {w0.x, w0.y, w0.z, w0.w, w1.x, w1.y, w1.z, w1.w};
#pragma unroll
        for (int i = 0; i < 8; i++)
#pragma unroll
            for (int j = 0; j < 8; j++) acc[i][j] += a[i] * w[j];
    }
#pragma unroll
    for (int i = 0; i < 8; i++) {
        float4 o0 = {acc[i][0], acc[i][1], acc[i][2], acc[i][3]};
        float4 o1 = {acc[i][4], acc[i][5], acc[i][6], acc[i][7]};
        float* d = g_h + (size_t)(node0 + r * 8 + i) * HD + c * 8;
        *(float4*)d = o0;
        *(float4*)(d + 4) = o1;
    }
}

// ---------------- copy h -> z (z then accumulates messages atomically) --------
__global__ void copy_kernel() {
    int base = blockIdx.x * 1024 + threadIdx.x;
    const float4* s = (const float4*)g_h;
    float4* d = (float4*)g_z;
#pragma unroll
    for (int t = 0; t < 4; t++) d[base + t * 256] = s[base + t * 256];
}

// ---------------- edge: m = relu(h[src] + ea@We + be); red-add into z[dst] ----
#define EPW 16
__global__ void edge_kernel(const int* __restrict__ src, const int* __restrict__ dst,
                            const float* __restrict__ ea,
                            const float* __restrict__ We, const float* __restrict__ be) {
    __shared__ float Wes[10 * HD];
    __shared__ float bes[HD];
    for (int i = threadIdx.x; i < 10 * HD; i += 256) Wes[i] = We[i];
    if (threadIdx.x < HD) bes[threadIdx.x] = be[threadIdx.x];
    __syncthreads();

    const int lane = threadIdx.x & 31;
    const int warp = threadIdx.x >> 5;
    const int e0 = (blockIdx.x * 8 + warp) * EPW;
    const float4 bev = *(const float4*)&bes[lane * 4];
    const float4* We4 = (const float4*)Wes;

    for (int t = 0; t < EPW; t++) {
        int e = e0 + t;
        if (e >= NE) break;
        float av = (lane < 10) ? ea[(size_t)e * 10 + lane] : 0.f;
        float4 acc = bev;
#pragma unroll
        for (int k = 0; k < 10; k++) {
            float a = __shfl_sync(0xffffffffu, av, k);
            float4 w = We4[k * 32 + lane];
            acc.x += a * w.x; acc.y += a * w.y; acc.z += a * w.z; acc.w += a * w.w;
        }
        int s = src[e], d = dst[e];
        float4 hv = *(const float4*)(g_h + (size_t)s * HD + lane * 4);
        float4 m;
        m.x = fmaxf(hv.x + acc.x, 0.f);
        m.y = fmaxf(hv.y + acc.y, 0.f);
        m.z = fmaxf(hv.z + acc.z, 0.f);
        m.w = fmaxf(hv.w + acc.w, 0.f);
        red_add_v4(g_z + (size_t)d * HD + lane * 4, m);
    }
}

// ---------------- node MLP: h = relu(BN(relu(z@W1+b1)@W2+b2)) -----------------
__global__ void __launch_bounds__(128, 1)
node_mlp_kernel(const float* __restrict__ W1, const float* __restrict__ b1,
                const float* __restrict__ W2, const float* __restrict__ b2,
                const float* __restrict__ gamma, const float* __restrict__ beta) {
    extern __shared__ float sm[];
    float* W1s = sm;              // 128*128
    float* W2s = sm + 16384;      // 128*128
    float* zt  = sm + 32768;      // 128*NMT (k-major), reused for t-tile
    const int tid = threadIdx.x;
    const int node0 = blockIdx.x * NMT;

    const float4* W1g = (const float4*)W1;
    const float4* W2g = (const float4*)W2;
    for (int i = tid; i < 4096; i += 128) {
        ((float4*)W1s)[i] = W1g[i];
        ((float4*)W2s)[i] = W2g[i];
    }
    {   // stage z tile transposed (k-major)
        int k4 = tid & 31, m0 = tid >> 5;
        for (int mm = m0; mm < NMT; mm += 4) {
            float4 v = *(const float4*)(g_z + (size_t)(node0 + mm) * HD + k4 * 4);
            zt[(k4 * 4 + 0) * NMT + mm] = v.x;
            zt[(k4 * 4 + 1) * NMT + mm] = v.y;
            zt[(k4 * 4 + 2) * NMT + mm] = v.z;
            zt[(k4 * 4 + 3) * NMT + mm] = v.w;
        }
    }
    __syncthreads();

    const int r = tid >> 4, c = tid & 15;
    float acc[8][8];
#pragma unroll
    for (int j = 0; j < 8; j++) {
        float bb = b1[c * 8 + j];
#pragma unroll
        for (int i = 0; i < 8; i++) acc[i][j] = bb;
    }
#pragma unroll 4
    for (int k = 0; k < HD; k++) {
        float4 a0 = *(float4*)&zt[k * NMT + r * 8];
        float4 a1 = *(float4*)&zt[k * NMT + r * 8 + 4];
        float4 w0 = *(float4*)&W1s[k * HD + c * 8];
        float4 w1 = *(float4*)&W1s[k * HD + c * 8 + 4];
        float a[8] = {a0.x, a0.y, a0.z, a0.w, a1.x, a1.y, a1.z, a1.w};
        float w[8] = {w0.x, w0.y, w0.z, w0.w, w1.x, w1.y, w1.z, w1.w};
#pragma unroll
        for (int i = 0; i < 8; i++)
#pragma unroll
            for (int j = 0; j < 8; j++) acc[i][j] += a[i] * w[j];
    }
    __syncthreads();   // everyone done reading zt
#pragma unroll
    for (int j = 0; j < 8; j++)
#pragma unroll
        for (int i = 0; i < 8; i++)
            zt[(c * 8 + j) * NMT + r * 8 + i] = fmaxf(acc[i][j], 0.f);
    __syncthreads();

#pragma unroll
    for (int j = 0; j < 8; j++) {
        float bb = b2[c * 8 + j];
#pragma unroll
        for (int i = 0; i < 8; i++) acc[i][j] = bb;
    }
#pragma unroll 4
    for (int k = 0; k < HD; k++) {
        float4 a0 = *(float4*)&zt[k * NMT + r * 8];
        float4 a1 = *(float4*)&zt[k * NMT + r * 8 + 4];
        float4 w0 = *(float4*)&W2s[k * HD + c * 8];
        float4 w1 = *(float4*)&W2s[k * HD + c * 8 + 4];
        float a[8] = {a0.x, a0.y, a0.z, a0.w, a1.x, a1.y, a1.z, a1.w};
        float w[8] = {w0.x, w0.y, w0.z, w0.w, w1.x, w1.y, w1.z, w1.w};
#pragma unroll
        for (int i = 0; i < 8; i++)
#pragma unroll
            for (int j = 0; j < 8; j++) acc[i][j] += a[i] * w[j];
    }

    const float inv_std = rsqrtf(1.0f + 1e-5f);
    float sc[8], bt[8];
#pragma unroll
    for (int j = 0; j < 8; j++) {
        sc[j] = gamma[c * 8 + j] * inv_std;
        bt[j] = beta[c * 8 + j];
    }
#pragma unroll
    for (int i = 0; i < 8; i++) {
        float o[8];
#pragma unroll
        for (int j = 0; j < 8; j++) o[j] = fmaxf(acc[i][j] * sc[j] + bt[j], 0.f);
        float* d = g_h + (size_t)(node0 + r * 8 + i) * HD + c * 8;
        *(float4*)d       = make_float4(o[0], o[1], o[2], o[3]);
        *(float4*)(d + 4) = make_float4(o[4], o[5], o[6], o[7]);
    }
}

// ---------------- pooling ----------------------------------------------------
__global__ void zero_pool_kernel() {
    int i = blockIdx.x * blockDim.x + threadIdx.x;
    float4 z = {0.f, 0.f, 0.f, 0.f};
    if (i < NG * HD / 4) ((float4*)g_sums)[i] = z;
    if (i < NG / 4) ((float4*)g_cnt)[i] = z;
}

__global__ void pool_kernel(const int* __restrict__ batch) {
    const int lane = threadIdx.x & 31, warp = threadIdx.x >> 5;
    const int n0 = (blockIdx.x * 8 + warp) * 32;
    if (n0 >= NN) return;
    const int nend = min(n0 + 32, NN);
    int curg = batch[n0];
    float4 acc = {0.f, 0.f, 0.f, 0.f};
    float cntv = 0.f;
    for (int n = n0; n < nend; n++) {
        int g = batch[n];
        if (g != curg) {
            red_add_v4(g_sums + (size_t)curg * HD + lane * 4, acc);
            if (lane == 0) atomicAdd(&g_cnt[curg], cntv);
            curg = g; acc = make_float4(0.f, 0.f, 0.f, 0.f); cntv = 0.f;
        }
        float4 hv = *(const float4*)(g_h + (size_t)n * HD + lane * 4);
        acc.x += hv.x; acc.y += hv.y; acc.z += hv.z; acc.w += hv.w;
        cntv += 1.f;
    }
    red_add_v4(g_sums + (size_t)curg * HD + lane * 4, acc);
    if (lane == 0) atomicAdd(&g_cnt[curg], cntv);
}

// ---------------- head: sigmoid(relu(p@Wh1+bh1)@Wh2+bh2) ----------------------
__global__ void head_kernel(const float* __restrict__ Wh1, const float* __restrict__ bh1,
                            const float* __restrict__ Wh2, const float* __restrict__ bh2,
                            float* __restrict__ out) {
    const int g = blockIdx.x, j = threadIdx.x;   // 64 threads
    __shared__ float ps[HD];
    __shared__ float redv[2];
    float rc = 1.0f / fmaxf(g_cnt[g], 1.0f);
    ps[j]      = g_sums[g * HD + j] * rc;
    ps[j + 64] = g_sums[g * HD + 64 + j] * rc;
    __syncthreads();
    float t = bh1[j];
#pragma unroll 8
    for (int k = 0; k < HD; k++) t += ps[k] * Wh1[k * 64 + j];
    t = fmaxf(t, 0.f) * Wh2[j];
#pragma unroll
    for (int o = 16; o > 0; o >>= 1) t += __shfl_down_sync(0xffffffffu, t, o);
    if ((j & 31) == 0) redv[j >> 5] = t;
    __syncthreads();
    if (j == 0) {
        float zv = redv[0] + redv[1] + bh2[0];
        out[g] = 1.0f / (1.0f + __expf(-zv));
    }
}

// ---------------- launch ------------------------------------------------------
extern "C" void kernel_launch(void* const* d_in, const int* in_sizes, int n_in,
                              void* d_out, int out_size) {
    const float* x      = (const float*)d_in[0];
    const int*   eidx   = (const int*)d_in[1];
    const float* eattr  = (const float*)d_in[2];
    const int*   batch  = (const int*)d_in[3];
    const float* W_enc  = (const float*)d_in[4];
    const float* b_enc  = (const float*)d_in[5];
    const float* We     = (const float*)d_in[6];
    const float* be     = (const float*)d_in[7];
    const float* W1     = (const float*)d_in[8];
    const float* b1     = (const float*)d_in[9];
    const float* W2     = (const float*)d_in[10];
    const float* b2     = (const float*)d_in[11];
    const float* gamma  = (const float*)d_in[12];
    const float* beta   = (const float*)d_in[13];
    const float* Wh1    = (const float*)d_in[14];
    const float* bh1    = (const float*)d_in[15];
    const float* Wh2    = (const float*)d_in[16];
    const float* bh2    = (const float*)d_in[17];
    float* out = (float*)d_out;

    const int enc_smem = (78 * HD + 78 * NMT) * 4;          // 59904 B
    const int mlp_smem = (2 * HD * HD + HD * NMT) * 4;      // 163840 B
    cudaFuncSetAttribute(encoder_kernel, cudaFuncAttributeMaxDynamicSharedMemorySize, enc_smem);
    cudaFuncSetAttribute(node_mlp_kernel, cudaFuncAttributeMaxDynamicSharedMemorySize, mlp_smem);

    encoder_kernel<<<NN / NMT, 128, enc_smem>>>(x, W_enc, b_enc);

    const int* src = eidx;
    const int* dst = eidx + NE;
    for (int l = 0; l < 3; l++) {
        copy_kernel<<<NN * HD / 4 / 1024, 256>>>();
        edge_kernel<<<NE / (8 * EPW), 256>>>(src, dst, eattr,
                                             We + (size_t)l * 10 * HD, be + (size_t)l * HD);
        node_mlp_kernel<<<NN / NMT, 128, mlp_smem>>>(W1 + (size_t)l * HD * HD, b1 + (size_t)l * HD,
                                                     W2 + (size_t)l * HD * HD, b2 + (size_t)l * HD,
                                                     gamma + (size_t)l * HD, beta + (size_t)l * HD);
    }
    zero_pool_kernel<<<(NG * HD / 4 + 255) / 256, 256>>>();
    pool_kernel<<<(NN + 255) / 256, 256>>>(batch);
    head_kernel<<<NG, 64>>>(Wh1, bh1, Wh2, bh2, out);
}

// round 4
// speedup vs baseline: 1.1421x; 1.1421x over previous
#include <cuda_runtime.h>
#include <math.h>

#define NN 200000
#define NE 800000
#define NG 8192
#define HD 128
#define ENT 64          // nodes per block tile: encoder
#define MNT 128         // nodes per block tile: node MLP

// ---------------- scratch (static device allocations; no cudaMalloc) ----------
__device__ float g_h[(size_t)NN * HD];     // node features          (~102 MB)
__device__ float g_z[(size_t)NN * HD];     // h + scattered messages (~102 MB)
__device__ float g_sums[NG * HD];          // pooled sums
__device__ float g_cnt[NG];                // pooled counts

__device__ __forceinline__ void red_add_v4(float* p, float4 v) {
    asm volatile("red.global.add.v4.f32 [%0], {%1,%2,%3,%4};"
                 :: "l"(p), "f"(v.x), "f"(v.y), "f"(v.z), "f"(v.w) : "memory");
}

// ---------------- encoder: h = x @ W_enc + b_enc  (K=78); writes g_h AND g_z --
__global__ void __launch_bounds__(128, 1)
encoder_kernel(const float* __restrict__ x,
               const float* __restrict__ W,
               const float* __restrict__ b) {
    extern __shared__ float sm[];
    float* Ws = sm;              // 78*128
    float* xt = Ws + 78 * HD;    // 78*ENT, k-major
    const int tid = threadIdx.x;
    const int node0 = blockIdx.x * ENT;

    const float4* Wg4 = (const float4*)W;
    float4* Ws4 = (float4*)Ws;
    for (int i = tid; i < 78 * (HD / 4); i += 128) Ws4[i] = Wg4[i];
    for (int idx = tid; idx < 78 * ENT; idx += 128) {
        int m = idx / 78, k = idx - m * 78;
        xt[k * ENT + m] = x[(size_t)(node0 + m) * 78 + k];
    }
    __syncthreads();

    const int r = tid >> 4, c = tid & 15;   // 8 r-rows x 16 c-cols of 8x8 tiles
    float acc[8][8];
#pragma unroll
    for (int j = 0; j < 8; j++) {
        float bb = b[c * 8 + j];
#pragma unroll
        for (int i = 0; i < 8; i++) acc[i][j] = bb;
    }
#pragma unroll 2
    for (int k = 0; k < 78; k++) {
        float4 a0 = *(float4*)&xt[k * ENT + r * 8];
        float4 a1 = *(float4*)&xt[k * ENT + r * 8 + 4];
        float4 w0 = *(float4*)&Ws[k * HD + c * 8];
        float4 w1 = *(float4*)&Ws[k * HD + c * 8 + 4];
        float a[8] = {a0.x, a0.y, a0.z, a0.w, a1.x, a1.y, a1.z, a1.w};
        float w[8] = {w0.x, w0.y, w0.z, w0.w, w1.x, w1.y, w1.z, w1.w};
#pragma unroll
        for (int i = 0; i < 8; i++)
#pragma unroll
            for (int j = 0; j < 8; j++) acc[i][j] += a[i] * w[j];
    }
#pragma unroll
    for (int i = 0; i < 8; i++) {
        float4 o0 = {acc[i][0], acc[i][1], acc[i][2], acc[i][3]};
        float4 o1 = {acc[i][4], acc[i][5], acc[i][6], acc[i][7]};
        size_t off = (size_t)(node0 + r * 8 + i) * HD + c * 8;
        *(float4*)(g_h + off)     = o0;
        *(float4*)(g_h + off + 4) = o1;
        *(float4*)(g_z + off)     = o0;   // pre-init scatter accumulator
        *(float4*)(g_z + off + 4) = o1;
    }
}

// ---------------- edge: m = relu(h[src] + ea@We + be); red-add into z[dst] ----
#define EPW 16
__global__ void edge_kernel(const int* __restrict__ src, const int* __restrict__ dst,
                            const float* __restrict__ ea,
                            const float* __restrict__ We, const float* __restrict__ be) {
    __shared__ float Wes[10 * HD];
    __shared__ float bes[HD];
    for (int i = threadIdx.x; i < 10 * HD; i += 256) Wes[i] = We[i];
    if (threadIdx.x < HD) bes[threadIdx.x] = be[threadIdx.x];
    __syncthreads();

    const int lane = threadIdx.x & 31;
    const int warp = threadIdx.x >> 5;
    const int e0 = (blockIdx.x * 8 + warp) * EPW;
    const float4 bev = *(const float4*)&bes[lane * 4];
    const float4* We4 = (const float4*)Wes;

    for (int t = 0; t < EPW; t++) {
        int e = e0 + t;
        if (e >= NE) break;
        float av = (lane < 10) ? ea[(size_t)e * 10 + lane] : 0.f;
        float4 acc = bev;
#pragma unroll
        for (int k = 0; k < 10; k++) {
            float a = __shfl_sync(0xffffffffu, av, k);
            float4 w = We4[k * 32 + lane];
            acc.x += a * w.x; acc.y += a * w.y; acc.z += a * w.z; acc.w += a * w.w;
        }
        int s = src[e], d = dst[e];
        float4 hv = *(const float4*)(g_h + (size_t)s * HD + lane * 4);
        float4 m;
        m.x = fmaxf(hv.x + acc.x, 0.f);
        m.y = fmaxf(hv.y + acc.y, 0.f);
        m.z = fmaxf(hv.z + acc.z, 0.f);
        m.w = fmaxf(hv.w + acc.w, 0.f);
        red_add_v4(g_z + (size_t)d * HD + lane * 4, m);
    }
}

// ---------------- node MLP: h = relu(BN(relu(z@W1+b1)@W2+b2)) -----------------
// 256 threads, 128-node tile, 8x8 micro-tiles. Writes g_h AND g_z.
__global__ void __launch_bounds__(256, 1)
node_mlp_kernel(const float* __restrict__ W1, const float* __restrict__ b1,
                const float* __restrict__ W2, const float* __restrict__ b2,
                const float* __restrict__ gamma, const float* __restrict__ beta,
                int write_z) {
    extern __shared__ float sm[];
    float* W1s = sm;              // 128*128
    float* W2s = sm + 16384;      // 128*128
    float* zt  = sm + 32768;      // 128*MNT (k-major), reused for t-tile
    const int tid = threadIdx.x;
    const int node0 = blockIdx.x * MNT;

    const float4* W1g = (const float4*)W1;
    const float4* W2g = (const float4*)W2;
    for (int i = tid; i < 4096; i += 256) {
        ((float4*)W1s)[i] = W1g[i];
        ((float4*)W2s)[i] = W2g[i];
    }
    {   // stage z tile transposed (k-major); clamp rows past NN
        int k4 = tid & 31, m0 = tid >> 5;
        for (int mm = m0; mm < MNT; mm += 8) {
            int row = node0 + mm; if (row >= NN) row = NN - 1;
            float4 v = *(const float4*)(g_z + (size_t)row * HD + k4 * 4);
            zt[(k4 * 4 + 0) * MNT + mm] = v.x;
            zt[(k4 * 4 + 1) * MNT + mm] = v.y;
            zt[(k4 * 4 + 2) * MNT + mm] = v.z;
            zt[(k4 * 4 + 3) * MNT + mm] = v.w;
        }
    }
    __syncthreads();

    const int r = tid >> 4, c = tid & 15;   // 16x16 of 8x8 tiles -> 128x128
    float acc[8][8];
#pragma unroll
    for (int j = 0; j < 8; j++) {
        float bb = b1[c * 8 + j];
#pragma unroll
        for (int i = 0; i < 8; i++) acc[i][j] = bb;
    }
#pragma unroll 4
    for (int k = 0; k < HD; k++) {
        float4 a0 = *(float4*)&zt[k * MNT + r * 8];
        float4 a1 = *(float4*)&zt[k * MNT + r * 8 + 4];
        float4 w0 = *(float4*)&W1s[k * HD + c * 8];
        float4 w1 = *(float4*)&W1s[k * HD + c * 8 + 4];
        float a[8] = {a0.x, a0.y, a0.z, a0.w, a1.x, a1.y, a1.z, a1.w};
        float w[8] = {w0.x, w0.y, w0.z, w0.w, w1.x, w1.y, w1.z, w1.w};
#pragma unroll
        for (int i = 0; i < 8; i++)
#pragma unroll
            for (int j = 0; j < 8; j++) acc[i][j] += a[i] * w[j];
    }
    __syncthreads();   // everyone done reading zt
#pragma unroll
    for (int j = 0; j < 8; j++)
#pragma unroll
        for (int i = 0; i < 8; i++)
            zt[(c * 8 + j) * MNT + r * 8 + i] = fmaxf(acc[i][j], 0.f);
    __syncthreads();

#pragma unroll
    for (int j = 0; j < 8; j++) {
        float bb = b2[c * 8 + j];
#pragma unroll
        for (int i = 0; i < 8; i++) acc[i][j] = bb;
    }
#pragma unroll 4
    for (int k = 0; k < HD; k++) {
        float4 a0 = *(float4*)&zt[k * MNT + r * 8];
        float4 a1 = *(float4*)&zt[k * MNT + r * 8 + 4];
        float4 w0 = *(float4*)&W2s[k * HD + c * 8];
        float4 w1 = *(float4*)&W2s[k * HD + c * 8 + 4];
        float a[8] = {a0.x, a0.y, a0.z, a0.w, a1.x, a1.y, a1.z, a1.w};
        float w[8] = {w0.x, w0.y, w0.z, w0.w, w1.x, w1.y, w1.z, w1.w};
#pragma unroll
        for (int i = 0; i < 8; i++)
#pragma unroll
            for (int j = 0; j < 8; j++) acc[i][j] += a[i] * w[j];
    }

    const float inv_std = rsqrtf(1.0f + 1e-5f);
    float sc[8], bt[8];
#pragma unroll
    for (int j = 0; j < 8; j++) {
        sc[j] = gamma[c * 8 + j] * inv_std;
        bt[j] = beta[c * 8 + j];
    }
#pragma unroll
    for (int i = 0; i < 8; i++) {
        int row = node0 + r * 8 + i;
        if (row >= NN) continue;
        float o[8];
#pragma unroll
        for (int j = 0; j < 8; j++) o[j] = fmaxf(acc[i][j] * sc[j] + bt[j], 0.f);
        float4 o0 = make_float4(o[0], o[1], o[2], o[3]);
        float4 o1 = make_float4(o[4], o[5], o[6], o[7]);
        size_t off = (size_t)row * HD + c * 8;
        *(float4*)(g_h + off)     = o0;
        *(float4*)(g_h + off + 4) = o1;
        if (write_z) {
            *(float4*)(g_z + off)     = o0;
            *(float4*)(g_z + off + 4) = o1;
        }
    }
}

// ---------------- pooling ----------------------------------------------------
__global__ void zero_pool_kernel() {
    int i = blockIdx.x * blockDim.x + threadIdx.x;
    float4 z = {0.f, 0.f, 0.f, 0.f};
    if (i < NG * HD / 4) ((float4*)g_sums)[i] = z;
    if (i < NG / 4) ((float4*)g_cnt)[i] = z;
}

__global__ void pool_kernel(const int* __restrict__ batch) {
    const int lane = threadIdx.x & 31, warp = threadIdx.x >> 5;
    const int n0 = (blockIdx.x * 8 + warp) * 32;
    if (n0 >= NN) return;
    const int nend = min(n0 + 32, NN);
    int curg = batch[n0];
    float4 acc = {0.f, 0.f, 0.f, 0.f};
    float cntv = 0.f;
    for (int n = n0; n < nend; n++) {
        int g = batch[n];
        if (g != curg) {
            red_add_v4(g_sums + (size_t)curg * HD + lane * 4, acc);
            if (lane == 0) atomicAdd(&g_cnt[curg], cntv);
            curg = g; acc = make_float4(0.f, 0.f, 0.f, 0.f); cntv = 0.f;
        }
        float4 hv = *(const float4*)(g_h + (size_t)n * HD + lane * 4);
        acc.x += hv.x; acc.y += hv.y; acc.z += hv.z; acc.w += hv.w;
        cntv += 1.f;
    }
    red_add_v4(g_sums + (size_t)curg * HD + lane * 4, acc);
    if (lane == 0) atomicAdd(&g_cnt[curg], cntv);
}

// ---------------- head: sigmoid(relu(p@Wh1+bh1)@Wh2+bh2) ----------------------
__global__ void head_kernel(const float* __restrict__ Wh1, const float* __restrict__ bh1,
                            const float* __restrict__ Wh2, const float* __restrict__ bh2,
                            float* __restrict__ out) {
    const int g = blockIdx.x, j = threadIdx.x;   // 64 threads
    __shared__ float ps[HD];
    __shared__ float redv[2];
    float rc = 1.0f / fmaxf(g_cnt[g], 1.0f);
    ps[j]      = g_sums[g * HD + j] * rc;
    ps[j + 64] = g_sums[g * HD + 64 + j] * rc;
    __syncthreads();
    float t = bh1[j];
#pragma unroll 8
    for (int k = 0; k < HD; k++) t += ps[k] * Wh1[k * 64 + j];
    t = fmaxf(t, 0.f) * Wh2[j];
#pragma unroll
    for (int o = 16; o > 0; o >>= 1) t += __shfl_down_sync(0xffffffffu, t, o);
    if ((j & 31) == 0) redv[j >> 5] = t;
    __syncthreads();
    if (j == 0) {
        float zv = redv[0] + redv[1] + bh2[0];
        out[g] = 1.0f / (1.0f + __expf(-zv));
    }
}

// ---------------- launch ------------------------------------------------------
extern "C" void kernel_launch(void* const* d_in, const int* in_sizes, int n_in,
                              void* d_out, int out_size) {
    const float* x      = (const float*)d_in[0];
    const int*   eidx   = (const int*)d_in[1];
    const float* eattr  = (const float*)d_in[2];
    const int*   batch  = (const int*)d_in[3];
    const float* W_enc  = (const float*)d_in[4];
    const float* b_enc  = (const float*)d_in[5];
    const float* We     = (const float*)d_in[6];
    const float* be     = (const float*)d_in[7];
    const float* W1     = (const float*)d_in[8];
    const float* b1     = (const float*)d_in[9];
    const float* W2     = (const float*)d_in[10];
    const float* b2     = (const float*)d_in[11];
    const float* gamma  = (const float*)d_in[12];
    const float* beta   = (const float*)d_in[13];
    const float* Wh1    = (const float*)d_in[14];
    const float* bh1    = (const float*)d_in[15];
    const float* Wh2    = (const float*)d_in[16];
    const float* bh2    = (const float*)d_in[17];
    float* out = (float*)d_out;

    const int enc_smem = (78 * HD + 78 * ENT) * 4;          // 59904 B
    const int mlp_smem = (2 * HD * HD + HD * MNT) * 4;      // 196608 B
    cudaFuncSetAttribute(encoder_kernel, cudaFuncAttributeMaxDynamicSharedMemorySize, enc_smem);
    cudaFuncSetAttribute(node_mlp_kernel, cudaFuncAttributeMaxDynamicSharedMemorySize, mlp_smem);

    encoder_kernel<<<NN / ENT, 128, enc_smem>>>(x, W_enc, b_enc);

    const int* src = eidx;
    const int* dst = eidx + NE;
    const int mlp_grid = (NN + MNT - 1) / MNT;
    for (int l = 0; l < 3; l++) {
        edge_kernel<<<NE / (8 * EPW), 256>>>(src, dst, eattr,
                                             We + (size_t)l * 10 * HD, be + (size_t)l * HD);
        node_mlp_kernel<<<mlp_grid, 256, mlp_smem>>>(W1 + (size_t)l * HD * HD, b1 + (size_t)l * HD,
                                                     W2 + (size_t)l * HD * HD, b2 + (size_t)l * HD,
                                                     gamma + (size_t)l * HD, beta + (size_t)l * HD,
                                                     l < 2 ? 1 : 0);
    }
    zero_pool_kernel<<<(NG * HD / 4 + 255) / 256, 256>>>();
    pool_kernel<<<(NN + 255) / 256, 256>>>(batch);
    head_kernel<<<NG, 64>>>(Wh1, bh1, Wh2, bh2, out);
}

// round 5
// speedup vs baseline: 1.1635x; 1.0188x over previous
#include <cuda_runtime.h>
#include <math.h>

#define NN 200000
#define NE 800000
#define NG 8192
#define HD 128
#define ENT 64          // nodes per block tile: encoder
#define MNT 256         // nodes per block tile: node MLP

// ---------------- scratch (static device allocations; no cudaMalloc) ----------
__device__ float g_h[(size_t)NN * HD];     // node features          (~102 MB)
__device__ float g_z[(size_t)NN * HD];     // h + scattered messages (~102 MB)
__device__ float g_sums[NG * HD];          // pooled sums
__device__ float g_cnt[NG];                // pooled counts

__device__ __forceinline__ void red_add_v4(float* p, float4 v) {
    asm volatile("red.global.add.v4.f32 [%0], {%1,%2,%3,%4};"
                 :: "l"(p), "f"(v.x), "f"(v.y), "f"(v.z), "f"(v.w) : "memory");
}

// ---------------- encoder: h = x @ W_enc + b_enc  (K=78); writes g_h AND g_z --
__global__ void __launch_bounds__(128, 1)
encoder_kernel(const float* __restrict__ x,
               const float* __restrict__ W,
               const float* __restrict__ b) {
    extern __shared__ float sm[];
    float* Ws = sm;              // 78*128
    float* xt = Ws + 78 * HD;    // 78*ENT, k-major
    const int tid = threadIdx.x;
    const int node0 = blockIdx.x * ENT;

    const float4* Wg4 = (const float4*)W;
    float4* Ws4 = (float4*)Ws;
    for (int i = tid; i < 78 * (HD / 4); i += 128) Ws4[i] = Wg4[i];
    for (int idx = tid; idx < 78 * ENT; idx += 128) {
        int m = idx / 78, k = idx - m * 78;
        xt[k * ENT + m] = x[(size_t)(node0 + m) * 78 + k];
    }
    __syncthreads();

    const int r = tid >> 4, c = tid & 15;
    float acc[8][8];
#pragma unroll
    for (int j = 0; j < 8; j++) {
        float bb = b[c * 8 + j];
#pragma unroll
        for (int i = 0; i < 8; i++) acc[i][j] = bb;
    }
#pragma unroll 2
    for (int k = 0; k < 78; k++) {
        float4 a0 = *(float4*)&xt[k * ENT + r * 8];
        float4 a1 = *(float4*)&xt[k * ENT + r * 8 + 4];
        float4 w0 = *(float4*)&Ws[k * HD + c * 8];
        float4 w1 = *(float4*)&Ws[k * HD + c * 8 + 4];
        float a[8] = {a0.x, a0.y, a0.z, a0.w, a1.x, a1.y, a1.z, a1.w};
        float w[8] = {w0.x, w0.y, w0.z, w0.w, w1.x, w1.y, w1.z, w1.w};
#pragma unroll
        for (int i = 0; i < 8; i++)
#pragma unroll
            for (int j = 0; j < 8; j++) acc[i][j] += a[i] * w[j];
    }
#pragma unroll
    for (int i = 0; i < 8; i++) {
        float4 o0 = {acc[i][0], acc[i][1], acc[i][2], acc[i][3]};
        float4 o1 = {acc[i][4], acc[i][5], acc[i][6], acc[i][7]};
        size_t off = (size_t)(node0 + r * 8 + i) * HD + c * 8;
        *(float4*)(g_h + off)     = o0;
        *(float4*)(g_h + off + 4) = o1;
        *(float4*)(g_z + off)     = o0;   // pre-init scatter accumulator
        *(float4*)(g_z + off + 4) = o1;
    }
}

// ---------------- edge: m = relu(h[src] + ea@We + be); red-add into z[dst] ----
// We column held in registers (loop-invariant); next edge prefetched.
#define EPW 16
__global__ void __launch_bounds__(256)
edge_kernel(const int* __restrict__ src, const int* __restrict__ dst,
            const float* __restrict__ ea,
            const float* __restrict__ We, const float* __restrict__ be) {
    __shared__ float Wes[10 * HD];
    for (int i = threadIdx.x; i < 10 * HD; i += 256) Wes[i] = We[i];
    __syncthreads();

    const int lane = threadIdx.x & 31;
    const int warp = threadIdx.x >> 5;
    const int e0 = (blockIdx.x * 8 + warp) * EPW;
    const float4 bev = *(const float4*)&be[lane * 4];
    const float4* We4 = (const float4*)Wes;

    float4 wreg[10];
#pragma unroll
    for (int k = 0; k < 10; k++) wreg[k] = We4[k * 32 + lane];

    // prime pipeline
    int s = src[e0], d = dst[e0];
    float av = (lane < 10) ? ea[(size_t)e0 * 10 + lane] : 0.f;
    float4 hv = *(const float4*)(g_h + (size_t)s * HD + lane * 4);

    for (int t = 0; t < EPW; t++) {
        int s2 = 0, d2 = 0; float av2 = 0.f; float4 hv2 = hv;
        if (t + 1 < EPW) {
            int e2 = e0 + t + 1;
            s2 = src[e2]; d2 = dst[e2];
            av2 = (lane < 10) ? ea[(size_t)e2 * 10 + lane] : 0.f;
            hv2 = *(const float4*)(g_h + (size_t)s2 * HD + lane * 4);
        }
        float4 acc = bev;
#pragma unroll
        for (int k = 0; k < 10; k++) {
            float a = __shfl_sync(0xffffffffu, av, k);
            acc.x += a * wreg[k].x; acc.y += a * wreg[k].y;
            acc.z += a * wreg[k].z; acc.w += a * wreg[k].w;
        }
        float4 m;
        m.x = fmaxf(hv.x + acc.x, 0.f);
        m.y = fmaxf(hv.y + acc.y, 0.f);
        m.z = fmaxf(hv.z + acc.z, 0.f);
        m.w = fmaxf(hv.w + acc.w, 0.f);
        red_add_v4(g_z + (size_t)d * HD + lane * 4, m);
        s = s2; d = d2; av = av2; hv = hv2;
    }
}

// ---------------- node MLP: h = relu(BN(relu(z@W1+b1)@W2+b2)) -----------------
// 512 threads, 256-node tile, 8x8 micro-tiles; single W buffer reloaded.
__global__ void __launch_bounds__(512, 1)
node_mlp_kernel(const float* __restrict__ W1, const float* __restrict__ b1,
                const float* __restrict__ W2, const float* __restrict__ b2,
                const float* __restrict__ gamma, const float* __restrict__ beta,
                int write_z) {
    extern __shared__ float sm[];
    float* Ws = sm;               // 128*128 (W1, then W2)
    float* zt = sm + 16384;       // 128*MNT (k-major), reused for t-tile
    const int tid = threadIdx.x;
    const int node0 = blockIdx.x * MNT;

    const float4* W1g = (const float4*)W1;
    const float4* W2g = (const float4*)W2;
    for (int i = tid; i < 4096; i += 512) ((float4*)Ws)[i] = W1g[i];
    {   // stage z tile transposed (k-major); clamp rows past NN
        int k4 = tid & 31, m0 = tid >> 5;   // m0 in 0..15
        for (int mm = m0; mm < MNT; mm += 16) {
            int row = node0 + mm; if (row >= NN) row = NN - 1;
            float4 v = *(const float4*)(g_z + (size_t)row * HD + k4 * 4);
            zt[(k4 * 4 + 0) * MNT + mm] = v.x;
            zt[(k4 * 4 + 1) * MNT + mm] = v.y;
            zt[(k4 * 4 + 2) * MNT + mm] = v.z;
            zt[(k4 * 4 + 3) * MNT + mm] = v.w;
        }
    }
    __syncthreads();

    const int r = tid >> 4, c = tid & 15;   // 32 x 16 of 8x8 tiles -> 256x128
    float acc[8][8];
#pragma unroll
    for (int j = 0; j < 8; j++) {
        float bb = b1[c * 8 + j];
#pragma unroll
        for (int i = 0; i < 8; i++) acc[i][j] = bb;
    }
#pragma unroll 4
    for (int k = 0; k < HD; k++) {
        float4 a0 = *(float4*)&zt[k * MNT + r * 8];
        float4 a1 = *(float4*)&zt[k * MNT + r * 8 + 4];
        float4 w0 = *(float4*)&Ws[k * HD + c * 8];
        float4 w1 = *(float4*)&Ws[k * HD + c * 8 + 4];
        float a[8] = {a0.x, a0.y, a0.z, a0.w, a1.x, a1.y, a1.z, a1.w};
        float w[8] = {w0.x, w0.y, w0.z, w0.w, w1.x, w1.y, w1.z, w1.w};
#pragma unroll
        for (int i = 0; i < 8; i++)
#pragma unroll
            for (int j = 0; j < 8; j++) acc[i][j] += a[i] * w[j];
    }
    __syncthreads();   // done reading zt and Ws(W1)
#pragma unroll
    for (int j = 0; j < 8; j++)
#pragma unroll
        for (int i = 0; i < 8; i++)
            zt[(c * 8 + j) * MNT + r * 8 + i] = fmaxf(acc[i][j], 0.f);
    for (int i = tid; i < 4096; i += 512) ((float4*)Ws)[i] = W2g[i];
    __syncthreads();

#pragma unroll
    for (int j = 0; j < 8; j++) {
        float bb = b2[c * 8 + j];
#pragma unroll
        for (int i = 0; i < 8; i++) acc[i][j] = bb;
    }
#pragma unroll 4
    for (int k = 0; k < HD; k++) {
        float4 a0 = *(float4*)&zt[k * MNT + r * 8];
        float4 a1 = *(float4*)&zt[k * MNT + r * 8 + 4];
        float4 w0 = *(float4*)&Ws[k * HD + c * 8];
        float4 w1 = *(float4*)&Ws[k * HD + c * 8 + 4];
        float a[8] = {a0.x, a0.y, a0.z, a0.w, a1.x, a1.y, a1.z, a1.w};
        float w[8] = {w0.x, w0.y, w0.z, w0.w, w1.x, w1.y, w1.z, w1.w};
#pragma unroll
        for (int i = 0; i < 8; i++)
#pragma unroll
            for (int j = 0; j < 8; j++) acc[i][j] += a[i] * w[j];
    }

    const float inv_std = rsqrtf(1.0f + 1e-5f);
    float sc[8], bt[8];
#pragma unroll
    for (int j = 0; j < 8; j++) {
        sc[j] = gamma[c * 8 + j] * inv_std;
        bt[j] = beta[c * 8 + j];
    }
#pragma unroll
    for (int i = 0; i < 8; i++) {
        int row = node0 + r * 8 + i;
        if (row >= NN) continue;
        float o[8];
#pragma unroll
        for (int j = 0; j < 8; j++) o[j] = fmaxf(acc[i][j] * sc[j] + bt[j], 0.f);
        float4 o0 = make_float4(o[0], o[1], o[2], o[3]);
        float4 o1 = make_float4(o[4], o[5], o[6], o[7]);
        size_t off = (size_t)row * HD + c * 8;
        *(float4*)(g_h + off)     = o0;
        *(float4*)(g_h + off + 4) = o1;
        if (write_z) {
            *(float4*)(g_z + off)     = o0;
            *(float4*)(g_z + off + 4) = o1;
        }
    }
}

// ---------------- pooling ----------------------------------------------------
__global__ void zero_pool_kernel() {
    int i = blockIdx.x * blockDim.x + threadIdx.x;
    float4 z = {0.f, 0.f, 0.f, 0.f};
    if (i < NG * HD / 4) ((float4*)g_sums)[i] = z;
    if (i < NG / 4) ((float4*)g_cnt)[i] = z;
}

__global__ void pool_kernel(const int* __restrict__ batch) {
    const int lane = threadIdx.x & 31, warp = threadIdx.x >> 5;
    const int n0 = (blockIdx.x * 8 + warp) * 32;
    if (n0 >= NN) return;
    const int nend = min(n0 + 32, NN);
    int curg = batch[n0];
    float4 acc = {0.f, 0.f, 0.f, 0.f};
    float cntv = 0.f;
    for (int n = n0; n < nend; n++) {
        int g = batch[n];
        if (g != curg) {
            red_add_v4(g_sums + (size_t)curg * HD + lane * 4, acc);
            if (lane == 0) atomicAdd(&g_cnt[curg], cntv);
            curg = g; acc = make_float4(0.f, 0.f, 0.f, 0.f); cntv = 0.f;
        }
        float4 hv = *(const float4*)(g_h + (size_t)n * HD + lane * 4);
        acc.x += hv.x; acc.y += hv.y; acc.z += hv.z; acc.w += hv.w;
        cntv += 1.f;
    }
    red_add_v4(g_sums + (size_t)curg * HD + lane * 4, acc);
    if (lane == 0) atomicAdd(&g_cnt[curg], cntv);
}

// ---------------- head: sigmoid(relu(p@Wh1+bh1)@Wh2+bh2) ----------------------
__global__ void head_kernel(const float* __restrict__ Wh1, const float* __restrict__ bh1,
                            const float* __restrict__ Wh2, const float* __restrict__ bh2,
                            float* __restrict__ out) {
    const int g = blockIdx.x, j = threadIdx.x;   // 64 threads
    __shared__ float ps[HD];
    __shared__ float redv[2];
    float rc = 1.0f / fmaxf(g_cnt[g], 1.0f);
    ps[j]      = g_sums[g * HD + j] * rc;
    ps[j + 64] = g_sums[g * HD + 64 + j] * rc;
    __syncthreads();
    float t = bh1[j];
#pragma unroll 8
    for (int k = 0; k < HD; k++) t += ps[k] * Wh1[k * 64 + j];
    t = fmaxf(t, 0.f) * Wh2[j];
#pragma unroll
    for (int o = 16; o > 0; o >>= 1) t += __shfl_down_sync(0xffffffffu, t, o);
    if ((j & 31) == 0) redv[j >> 5] = t;
    __syncthreads();
    if (j == 0) {
        float zv = redv[0] + redv[1] + bh2[0];
        out[g] = 1.0f / (1.0f + __expf(-zv));
    }
}

// ---------------- launch ------------------------------------------------------
extern "C" void kernel_launch(void* const* d_in, const int* in_sizes, int n_in,
                              void* d_out, int out_size) {
    const float* x      = (const float*)d_in[0];
    const int*   eidx   = (const int*)d_in[1];
    const float* eattr  = (const float*)d_in[2];
    const int*   batch  = (const int*)d_in[3];
    const float* W_enc  = (const float*)d_in[4];
    const float* b_enc  = (const float*)d_in[5];
    const float* We     = (const float*)d_in[6];
    const float* be     = (const float*)d_in[7];
    const float* W1     = (const float*)d_in[8];
    const float* b1     = (const float*)d_in[9];
    const float* W2     = (const float*)d_in[10];
    const float* b2     = (const float*)d_in[11];
    const float* gamma  = (const float*)d_in[12];
    const float* beta   = (const float*)d_in[13];
    const float* Wh1    = (const float*)d_in[14];
    const float* bh1    = (const float*)d_in[15];
    const float* Wh2    = (const float*)d_in[16];
    const float* bh2    = (const float*)d_in[17];
    float* out = (float*)d_out;

    const int enc_smem = (78 * HD + 78 * ENT) * 4;          // 59904 B
    const int mlp_smem = (HD * HD + HD * MNT) * 4;          // 196608 B
    cudaFuncSetAttribute(encoder_kernel, cudaFuncAttributeMaxDynamicSharedMemorySize, enc_smem);
    cudaFuncSetAttribute(node_mlp_kernel, cudaFuncAttributeMaxDynamicSharedMemorySize, mlp_smem);

    encoder_kernel<<<NN / ENT, 128, enc_smem>>>(x, W_enc, b_enc);

    const int* src = eidx;
    const int* dst = eidx + NE;
    const int mlp_grid = (NN + MNT - 1) / MNT;
    for (int l = 0; l < 3; l++) {
        edge_kernel<<<NE / (8 * EPW), 256>>>(src, dst, eattr,
                                             We + (size_t)l * 10 * HD, be + (size_t)l * HD);
        node_mlp_kernel<<<mlp_grid, 512, mlp_smem>>>(W1 + (size_t)l * HD * HD, b1 + (size_t)l * HD,
                                                     W2 + (size_t)l * HD * HD, b2 + (size_t)l * HD,
                                                     gamma + (size_t)l * HD, beta + (size_t)l * HD,
                                                     l < 2 ? 1 : 0);
    }
    zero_pool_kernel<<<(NG * HD / 4 + 255) / 256, 256>>>();
    pool_kernel<<<(NN + 255) / 256, 256>>>(batch);
    head_kernel<<<NG, 64>>>(Wh1, bh1, Wh2, bh2, out);
}